// round 7
// baseline (speedup 1.0000x reference)
#include <cuda_runtime.h>
#include <math.h>

// Problem constants (fixed by the dataset)
#define B_ 4
#define S_ 256
#define E_ 256
#define H_ 128
#define N_ (B_ * S_)   // 1024 rows total

// Scratch (static device arrays; allocation-free per harness rules)
__device__ float g_ampq[N_ * E_];
__device__ float g_ampk[N_ * E_];
__device__ float g_V[N_ * H_];
__device__ float g_Pq[N_ * E_];   // row-major, query side
__device__ float g_Pk[N_ * E_];   // row-major, key side
__device__ float g_entq[N_];      // sum_e P * lg2(P + 1e-10)
__device__ float g_entk[N_];

// ---- packed f32x2 helper (sm_100a): d = a*b + d on two lanes ---------------
__device__ __forceinline__ void ffma2(unsigned long long& acc,
                                      unsigned long long a,
                                      unsigned long long b) {
    asm("fma.rn.f32x2 %0, %1, %2, %0;" : "+l"(acc) : "l"(a), "l"(b));
}
__device__ __forceinline__ float2 unpk2(unsigned long long p) {
    float2 r;
    asm("mov.b64 {%0, %1}, %2;" : "=f"(r.x), "=f"(r.y) : "l"(p));
    return r;
}

// ---------------------------------------------------------------------------
// Kernel 1: C[1024, 640] = x[1024,256] @ [Wq;Wk;Wv]^T   (region per f-tile)
// 32x64 CTA tile, 256 threads, 2x4 micro-tile, ALL math via fma.rn.f32x2.
// A is stored DUPLICATED in smem ((a,a) pairs) so one LDS.128 delivers two
// packed f32x2 multiplicands and zero packing movs are needed; B's float4
// reinterprets directly as two b64. Inner loop = 2 LDS.128 + 4 FFMA2.
// Global->smem is double-buffered with register prefetch; 1 sync per chunk.
// Grid 320 CTAs (~2.2 waves), ~3 CTAs resident/SM.
// ---------------------------------------------------------------------------
__global__ __launch_bounds__(256) void k1_gemm(
    const float* __restrict__ x,
    const float* __restrict__ Wq,
    const float* __restrict__ Wk,
    const float* __restrict__ Wv)
{
    __shared__ __align__(16) float As[2][32][68];  // [buf][k][2*m dup], stride 68 (16B rows)
    __shared__ __align__(16) float Bs[2][32][68];  // [buf][k][f]

    const int m0 = blockIdx.x * 32;       // row tile (0..31)
    const int f0 = blockIdx.y * 64;       // f tile (0..9) over concat 640

    const float* Wp; float* outp; int fo, ostride;
    if (f0 < 256)      { Wp = Wq; fo = f0;       outp = g_ampq; ostride = E_; }
    else if (f0 < 512) { Wp = Wk; fo = f0 - 256; outp = g_ampk; ostride = E_; }
    else               { Wp = Wv; fo = f0 - 512; outp = g_V;    ostride = H_; }

    const int tid = threadIdx.x;
    const int tx  = tid & 15;             // f micro (4 cols)
    const int ty  = tid >> 4;             // m micro (2 rows), 0..15

    // Loader mapping (coalesced LDG)
    const int arow = tid >> 3;            // 0..31  (A: 1 float4 / thread / chunk)
    const int ak   = (tid & 7) * 4;
    const int brow = tid >> 2;            // 0..63  (B: 2 float4 / thread / chunk)
    const int bk   = (tid & 3) * 8;

    const float* xg = x  + (m0 + arow) * E_ + ak;
    const float* wg = Wp + (fo + brow) * E_ + bk;

    unsigned long long c00 = 0ull, c01 = 0ull, c10 = 0ull, c11 = 0ull;

    // Preload chunk 0 into regs, stage into buffer 0.
    float4 pa  = *(const float4*)(xg);
    float4 pb0 = *(const float4*)(wg);
    float4 pb1 = *(const float4*)(wg + 4);
    {
        As[0][ak+0][arow*2] = pa.x; As[0][ak+0][arow*2+1] = pa.x;
        As[0][ak+1][arow*2] = pa.y; As[0][ak+1][arow*2+1] = pa.y;
        As[0][ak+2][arow*2] = pa.z; As[0][ak+2][arow*2+1] = pa.z;
        As[0][ak+3][arow*2] = pa.w; As[0][ak+3][arow*2+1] = pa.w;
        Bs[0][bk+0][brow] = pb0.x; Bs[0][bk+1][brow] = pb0.y;
        Bs[0][bk+2][brow] = pb0.z; Bs[0][bk+3][brow] = pb0.w;
        Bs[0][bk+4][brow] = pb1.x; Bs[0][bk+5][brow] = pb1.y;
        Bs[0][bk+6][brow] = pb1.z; Bs[0][bk+7][brow] = pb1.w;
    }
    __syncthreads();

    #pragma unroll
    for (int c = 0; c < 8; c++) {
        const int buf = c & 1;
        if (c < 7) {                       // issue next-chunk LDGs early
            const int k0 = (c + 1) * 32;
            pa  = *(const float4*)(xg + k0);
            pb0 = *(const float4*)(wg + k0);
            pb1 = *(const float4*)(wg + k0 + 4);
        }

        #pragma unroll
        for (int kk = 0; kk < 32; kk++) {
            ulonglong2 a2 = *(const ulonglong2*)&As[buf][kk][ty * 4];
            ulonglong2 b2 = *(const ulonglong2*)&Bs[buf][kk][tx * 4];
            ffma2(c00, a2.x, b2.x);
            ffma2(c01, a2.x, b2.y);
            ffma2(c10, a2.y, b2.x);
            ffma2(c11, a2.y, b2.y);
        }

        if (c < 7) {                       // stage next chunk, single sync
            const int nb = buf ^ 1;
            As[nb][ak+0][arow*2] = pa.x; As[nb][ak+0][arow*2+1] = pa.x;
            As[nb][ak+1][arow*2] = pa.y; As[nb][ak+1][arow*2+1] = pa.y;
            As[nb][ak+2][arow*2] = pa.z; As[nb][ak+2][arow*2+1] = pa.z;
            As[nb][ak+3][arow*2] = pa.w; As[nb][ak+3][arow*2+1] = pa.w;
            Bs[nb][bk+0][brow] = pb0.x; Bs[nb][bk+1][brow] = pb0.y;
            Bs[nb][bk+2][brow] = pb0.z; Bs[nb][bk+3][brow] = pb0.w;
            Bs[nb][bk+4][brow] = pb1.x; Bs[nb][bk+5][brow] = pb1.y;
            Bs[nb][bk+6][brow] = pb1.z; Bs[nb][bk+7][brow] = pb1.w;
            __syncthreads();
        }
    }

    float2 u00 = unpk2(c00), u01 = unpk2(c01);
    float2 u10 = unpk2(c10), u11 = unpk2(c11);
    const int r0 = m0 + ty * 2;
    *(float4*)&outp[ r0      * ostride + fo + tx * 4] =
        make_float4(u00.x, u00.y, u01.x, u01.y);
    *(float4*)&outp[(r0 + 1) * ostride + fo + tx * 4] =
        make_float4(u10.x, u10.y, u11.x, u11.y);
}

// ---------------------------------------------------------------------------
// Kernel 2: warp-per-row probs + entropy.  Each warp owns one (row, region):
// P = amp^2 / (ssq_amp + EPS*d^2), d = ||x_n|| + 1e-12 (psi-norm folded in),
// ent = sum P*lg2(P+EPS).  Warp-only shfl butterflies, no __syncthreads,
// all loads/stores coalesced (row-major outputs).
// grid 256 CTAs x 256 threads (8 warps = 8 row-slots each).
// ---------------------------------------------------------------------------
__global__ __launch_bounds__(256) void k2_probs(const float* __restrict__ x)
{
    const int w    = threadIdx.x >> 5;
    const int lane = threadIdx.x & 31;
    const int slot = blockIdx.x * 8 + w;       // 0..2047
    const int regn = slot >> 10;               // 0 = q, 1 = k
    const int n    = slot & 1023;

    const float* amp  = (regn ? g_ampk : g_ampq) + n * E_;
    float*       Pout = (regn ? g_Pk   : g_Pq)   + n * E_;
    const float* xr   = x + n * E_;

    float a[8];
    float ssa = 0.f, ssx = 0.f;
    #pragma unroll
    for (int m = 0; m < 8; m++) {
        a[m] = amp[lane + 32 * m];
        float xv = xr[lane + 32 * m];
        ssa = fmaf(a[m], a[m], ssa);
        ssx = fmaf(xv, xv, ssx);
    }
    #pragma unroll
    for (int o = 16; o; o >>= 1) {
        ssa += __shfl_xor_sync(0xffffffffu, ssa, o);
        ssx += __shfl_xor_sync(0xffffffffu, ssx, o);
    }
    const float d   = sqrtf(ssx) + 1e-12f;
    const float inv = 1.0f / (ssa + 1e-10f * d * d);

    float ent = 0.f;
    #pragma unroll
    for (int m = 0; m < 8; m++) {
        const float P = a[m] * a[m] * inv;
        ent = fmaf(P, __log2f(P + 1e-10f), ent);
        Pout[lane + 32 * m] = P;
    }
    #pragma unroll
    for (int o = 16; o; o >>= 1)
        ent += __shfl_xor_sync(0xffffffffu, ent, o);
    if (lane == 0) (regn ? g_entk : g_entq)[n] = ent;
}

// ---------------------------------------------------------------------------
// Kernel 3: fused JS score + causal row-normalize + attn @ V.
// One CTA handles FOUR adjacent query rows of one batch: each Pk row load is
// reused 4x (LDG traffic / 4).  Warp-per-j, P rows register-resident,
// butterfly reduction.  256 CTAs x 256 threads.  MUFU(lg2)-bound core.
// ---------------------------------------------------------------------------
__global__ __launch_bounds__(256) void k3_attn(float* __restrict__ out)
{
    __shared__ float sScore[4][256];
    __shared__ float sO[4][128];
    __shared__ float sred[4][8];
    __shared__ float sInv[4];

    const int c  = blockIdx.x;        // 0..255
    const int n0 = c * 4;
    const int b  = n0 >> 8;
    const int i0 = n0 & 255;          // rows i0..i0+3
    const int i3 = i0 + 3;
    const int tid  = threadIdx.x;
    const int w    = tid >> 5;
    const int lane = tid & 31;

    // Register-resident P rows for the four queries (per-warp copy, coalesced).
    float p[4][8];
    const float* Pq0 = g_Pq + n0 * E_;
    #pragma unroll
    for (int r = 0; r < 4; r++)
        #pragma unroll
        for (int m = 0; m < 8; m++)
            p[r][m] = Pq0[r * E_ + lane + 32 * m];

    float hq[4];
    #pragma unroll
    for (int r = 0; r < 4; r++) hq[r] = g_entq[n0 + r];

    const float* Pkb   = g_Pk   + b * S_ * E_;
    const float* entkb = g_entk + b * S_;

    for (int j = w; j <= i3; j += 8) {
        const float* Qr = Pkb + j * E_;
        float acc[4] = {0.f, 0.f, 0.f, 0.f};
        #pragma unroll
        for (int m = 0; m < 8; m++) {
            const float q = Qr[lane + 32 * m];
            #pragma unroll
            for (int r = 0; r < 4; r++) {
                const float s = p[r][m] + q;
                acc[r] = fmaf(s, __log2f(fmaf(0.5f, s, 1e-10f)), acc[r]);
            }
        }
        #pragma unroll
        for (int o = 16; o; o >>= 1)
            #pragma unroll
            for (int r = 0; r < 4; r++)
                acc[r] += __shfl_xor_sync(0xffffffffu, acc[r], o);
        if (lane == 0) {
            const float HL = 0.34657359028f;   // 0.5 * ln(2)
            const float hk = entkb[j];
            #pragma unroll
            for (int r = 0; r < 4; r++) {
                const float js = HL * (hq[r] + hk - acc[r]);
                sScore[r][j] = (j <= i0 + r) ? (1.0f - js) : 0.0f;
            }
        }
    }
    __syncthreads();

    // Row L1-normalization sums (masked entries are exactly 0).
    {
        float v[4];
        #pragma unroll
        for (int r = 0; r < 4; r++)
            v[r] = (tid <= i0 + r) ? fabsf(sScore[r][tid]) : 0.f;
        #pragma unroll
        for (int o = 16; o; o >>= 1)
            #pragma unroll
            for (int r = 0; r < 4; r++)
                v[r] += __shfl_xor_sync(0xffffffffu, v[r], o);
        if (lane == 0)
            #pragma unroll
            for (int r = 0; r < 4; r++) sred[r][w] = v[r];
        __syncthreads();
        if (tid < 4) {
            float s = 0.f;
            #pragma unroll
            for (int k = 0; k < 8; k++) s += sred[tid][k];
            sInv[tid] = 1.0f / fmaxf(s, 1e-12f);
        }
        __syncthreads();
    }

    // out[i,h] = inv * sum_{j<=i} score[j] * V[j,h]; split j over 2 halves.
    const int half = tid >> 7;
    const int h    = tid & 127;
    const float* Vb = g_V + b * S_ * H_;
    float a[4] = {0.f, 0.f, 0.f, 0.f};
    for (int j = half; j <= i3; j += 2) {
        const float v = Vb[j * H_ + h];
        #pragma unroll
        for (int r = 0; r < 4; r++)
            a[r] = fmaf(sScore[r][j], v, a[r]);   // masked scores are 0
    }
    if (half == 1)
        #pragma unroll
        for (int r = 0; r < 4; r++) sO[r][h] = a[r];
    __syncthreads();
    if (half == 0)
        #pragma unroll
        for (int r = 0; r < 4; r++)
            out[(n0 + r) * H_ + h] = (a[r] + sO[r][h]) * sInv[r];
}

// ---------------------------------------------------------------------------
// Launch. Inputs per metadata order: x, Wv, Wq, Wk (all float32).
// ---------------------------------------------------------------------------
extern "C" void kernel_launch(void* const* d_in, const int* in_sizes, int n_in,
                              void* d_out, int out_size)
{
    const float* x  = (const float*)d_in[0];
    const float* Wv = (const float*)d_in[1];
    const float* Wq = (const float*)d_in[2];
    const float* Wk = (const float*)d_in[3];
    float* out = (float*)d_out;

    k1_gemm<<<dim3(32, 10), 256>>>(x, Wq, Wk, Wv);
    k2_probs<<<256, 256>>>(x);
    k3_attn<<<256, 256>>>(out);
}

// round 8
// speedup vs baseline: 2.1160x; 2.1160x over previous
#include <cuda_runtime.h>
#include <math.h>

// Problem constants (fixed by the dataset)
#define B_ 4
#define S_ 256
#define E_ 256
#define H_ 128
#define N_ (B_ * S_)   // 1024 rows total

// Scratch (static device arrays; allocation-free per harness rules)
// Split-K partial buffers: index [z] = K-half
__device__ float g_ampq2[2][N_ * E_];
__device__ float g_ampk2[2][N_ * E_];
__device__ float g_V2[2][N_ * H_];
__device__ float g_V[N_ * H_];
__device__ float g_Pq[N_ * E_];   // row-major, query side
__device__ float g_Pk[N_ * E_];   // row-major, key side
__device__ float g_entq[N_];      // sum_e P * lg2(P + 1e-10)
__device__ float g_entk[N_];

// ---------------------------------------------------------------------------
// Kernel 1: split-K GEMM.  C[1024, 640] = x[1024,256] @ [Wq;Wk;Wv]^T.
// Identical tiling to the proven round-5 kernel (64x64 CTA tile, 256 thr,
// 4x4 micro, 16 FFMA per 2 LDS.128) but each CTA computes only half of K
// (z = blockIdx.z selects K range) into a partial buffer.  Grid 16x10x2 =
// 320 CTAs -> 17.3 warps/SM (vs 8.6), saturating the FMA pipe instead of
// sitting grid-limited.  Partials are summed for free inside k2.
// ---------------------------------------------------------------------------
__global__ __launch_bounds__(256) void k1_gemm(
    const float* __restrict__ x,
    const float* __restrict__ Wq,
    const float* __restrict__ Wk,
    const float* __restrict__ Wv)
{
    __shared__ float As[32][68];  // [k][m], pad keeps float4 alignment
    __shared__ float Bs[32][68];  // [k][f]

    const int m0 = blockIdx.x * 64;       // row tile (0..15)
    const int f0 = blockIdx.y * 64;       // f tile (0..9) over concat 640
    const int z  = blockIdx.z;            // K half (0: k<128, 1: k>=128)
    const int kbase = z * 128;

    const float* Wp; float* outp; int fo, ostride;
    if (f0 < 256)      { Wp = Wq; fo = f0;       outp = g_ampq2[z]; ostride = E_; }
    else if (f0 < 512) { Wp = Wk; fo = f0 - 256; outp = g_ampk2[z]; ostride = E_; }
    else               { Wp = Wv; fo = f0 - 512; outp = g_V2[z];    ostride = H_; }

    const int tid  = threadIdx.x;
    const int tx   = tid & 15;            // f micro
    const int ty   = tid >> 4;            // m micro
    const int lrow = tid >> 2;            // 0..63 loader row
    const int lk   = (tid & 3) * 8;       // 0,8,16,24 loader k base

    const float* xg = x  + (m0 + lrow) * E_ + kbase + lk;
    const float* wg = Wp + (fo + lrow) * E_ + kbase + lk;

    float acc[4][4] = {};

    for (int k0 = 0; k0 < 128; k0 += 32) {
        float4 a0 = *(const float4*)(xg + k0);
        float4 a1 = *(const float4*)(xg + k0 + 4);
        float4 b0 = *(const float4*)(wg + k0);
        float4 b1 = *(const float4*)(wg + k0 + 4);
        As[lk+0][lrow] = a0.x; As[lk+1][lrow] = a0.y;
        As[lk+2][lrow] = a0.z; As[lk+3][lrow] = a0.w;
        As[lk+4][lrow] = a1.x; As[lk+5][lrow] = a1.y;
        As[lk+6][lrow] = a1.z; As[lk+7][lrow] = a1.w;
        Bs[lk+0][lrow] = b0.x; Bs[lk+1][lrow] = b0.y;
        Bs[lk+2][lrow] = b0.z; Bs[lk+3][lrow] = b0.w;
        Bs[lk+4][lrow] = b1.x; Bs[lk+5][lrow] = b1.y;
        Bs[lk+6][lrow] = b1.z; Bs[lk+7][lrow] = b1.w;
        __syncthreads();

        #pragma unroll
        for (int kk = 0; kk < 32; kk++) {
            float4 av = *(const float4*)&As[kk][ty * 4];
            float4 bv = *(const float4*)&Bs[kk][tx * 4];
            acc[0][0] = fmaf(av.x, bv.x, acc[0][0]);
            acc[0][1] = fmaf(av.x, bv.y, acc[0][1]);
            acc[0][2] = fmaf(av.x, bv.z, acc[0][2]);
            acc[0][3] = fmaf(av.x, bv.w, acc[0][3]);
            acc[1][0] = fmaf(av.y, bv.x, acc[1][0]);
            acc[1][1] = fmaf(av.y, bv.y, acc[1][1]);
            acc[1][2] = fmaf(av.y, bv.z, acc[1][2]);
            acc[1][3] = fmaf(av.y, bv.w, acc[1][3]);
            acc[2][0] = fmaf(av.z, bv.x, acc[2][0]);
            acc[2][1] = fmaf(av.z, bv.y, acc[2][1]);
            acc[2][2] = fmaf(av.z, bv.z, acc[2][2]);
            acc[2][3] = fmaf(av.z, bv.w, acc[2][3]);
            acc[3][0] = fmaf(av.w, bv.x, acc[3][0]);
            acc[3][1] = fmaf(av.w, bv.y, acc[3][1]);
            acc[3][2] = fmaf(av.w, bv.z, acc[3][2]);
            acc[3][3] = fmaf(av.w, bv.w, acc[3][3]);
        }
        __syncthreads();
    }

    #pragma unroll
    for (int i = 0; i < 4; i++) {
        const int row = m0 + ty * 4 + i;
        float4 v = make_float4(acc[i][0], acc[i][1], acc[i][2], acc[i][3]);
        *(float4*)&outp[row * ostride + fo + tx * 4] = v;
    }
}

// ---------------------------------------------------------------------------
// Kernel 2: warp-per-row.  Regions 0/1 (q/k): amp = part0 + part1 (split-K
// combine), then P = amp^2 / (ssq_amp + EPS*d^2), d = ||x_n|| + 1e-12
// (psi-norm folded in), ent = sum P*lg2(P+EPS).  Region 2: V = V0 + V1.
// Warp-only shfl butterflies, no __syncthreads, coalesced I/O.
// grid 384 CTAs x 256 threads = 3072 warp-slots.
// ---------------------------------------------------------------------------
__global__ __launch_bounds__(256) void k2_probs(const float* __restrict__ x)
{
    const int w    = threadIdx.x >> 5;
    const int lane = threadIdx.x & 31;
    const int slot = blockIdx.x * 8 + w;       // 0..3071
    const int regn = slot >> 10;               // 0 = q, 1 = k, 2 = V-combine
    const int n    = slot & 1023;

    if (regn == 2) {
        const float4* v0 = (const float4*)&g_V2[0][n * H_];
        const float4* v1 = (const float4*)&g_V2[1][n * H_];
        float4*       vo = (float4*)&g_V[n * H_];
        const float4 a = v0[lane], b = v1[lane];
        vo[lane] = make_float4(a.x + b.x, a.y + b.y, a.z + b.z, a.w + b.w);
        return;
    }

    const float* a0 = (regn ? g_ampk2[0] : g_ampq2[0]) + n * E_;
    const float* a1 = (regn ? g_ampk2[1] : g_ampq2[1]) + n * E_;
    float*     Pout = (regn ? g_Pk       : g_Pq)       + n * E_;
    const float* xr = x + n * E_;

    float a[8];
    float ssa = 0.f, ssx = 0.f;
    #pragma unroll
    for (int m = 0; m < 8; m++) {
        a[m] = a0[lane + 32 * m] + a1[lane + 32 * m];
        float xv = xr[lane + 32 * m];
        ssa = fmaf(a[m], a[m], ssa);
        ssx = fmaf(xv, xv, ssx);
    }
    #pragma unroll
    for (int o = 16; o; o >>= 1) {
        ssa += __shfl_xor_sync(0xffffffffu, ssa, o);
        ssx += __shfl_xor_sync(0xffffffffu, ssx, o);
    }
    const float d   = sqrtf(ssx) + 1e-12f;
    const float inv = 1.0f / (ssa + 1e-10f * d * d);

    float ent = 0.f;
    #pragma unroll
    for (int m = 0; m < 8; m++) {
        const float P = a[m] * a[m] * inv;
        ent = fmaf(P, __log2f(P + 1e-10f), ent);
        Pout[lane + 32 * m] = P;
    }
    #pragma unroll
    for (int o = 16; o; o >>= 1)
        ent += __shfl_xor_sync(0xffffffffu, ent, o);
    if (lane == 0) (regn ? g_entk : g_entq)[n] = ent;
}

// ---------------------------------------------------------------------------
// Kernel 3 (round-5 proven version): fused JS score + causal row-normalize +
// attn @ V.  One CTA handles two adjacent query rows (i0, i1=i0+1); Q row
// loads reused for both.  Warp-per-j, P rows register-resident, shfl
// reduction.  512 CTAs x 256 threads.
// ---------------------------------------------------------------------------
__global__ __launch_bounds__(256) void k3_attn(float* __restrict__ out)
{
    __shared__ float sScore[2][256];
    __shared__ float sO[2][128];
    __shared__ float sred[2][8];
    __shared__ float sInv[2];

    const int c  = blockIdx.x;        // 0..511
    const int n0 = c * 2;
    const int b  = n0 >> 8;
    const int i0 = n0 & 255;
    const int i1 = i0 + 1;
    const int tid  = threadIdx.x;
    const int w    = tid >> 5;
    const int lane = tid & 31;

    // Register-resident P rows for the two queries (per-warp copy, coalesced).
    float p0[8], p1[8];
    const float* Pq0 = g_Pq + n0 * E_;
    #pragma unroll
    for (int m = 0; m < 8; m++) {
        p0[m] = Pq0[lane + 32 * m];
        p1[m] = Pq0[E_ + lane + 32 * m];
    }
    const float hq0 = g_entq[n0];
    const float hq1 = g_entq[n0 + 1];
    const float* Pkb   = g_Pk   + b * S_ * E_;
    const float* entkb = g_entk + b * S_;

    for (int j = w; j <= i1; j += 8) {
        const float* Qr = Pkb + j * E_;
        float acc0 = 0.f, acc1 = 0.f;
        #pragma unroll
        for (int m = 0; m < 8; m++) {
            float q  = Qr[lane + 32 * m];
            float s0 = p0[m] + q;
            float s1 = p1[m] + q;
            acc0 = fmaf(s0, __log2f(fmaf(0.5f, s0, 1e-10f)), acc0);
            acc1 = fmaf(s1, __log2f(fmaf(0.5f, s1, 1e-10f)), acc1);
        }
        #pragma unroll
        for (int o = 16; o; o >>= 1) {
            acc0 += __shfl_xor_sync(0xffffffffu, acc0, o);
            acc1 += __shfl_xor_sync(0xffffffffu, acc1, o);
        }
        if (lane == 0) {
            const float HL = 0.34657359028f;   // 0.5 * ln(2)
            float hk  = entkb[j];
            float js0 = HL * (hq0 + hk - acc0);
            float js1 = HL * (hq1 + hk - acc1);
            sScore[0][j] = (j <= i0) ? (1.0f - js0) : 0.0f;  // causal mask row i0
            sScore[1][j] = 1.0f - js1;
        }
    }
    __syncthreads();

    // Row L1-normalization sums.
    float v0 = (tid <= i0) ? fabsf(sScore[0][tid]) : 0.f;
    float v1 = (tid <= i1) ? fabsf(sScore[1][tid]) : 0.f;
    #pragma unroll
    for (int o = 16; o; o >>= 1) {
        v0 += __shfl_xor_sync(0xffffffffu, v0, o);
        v1 += __shfl_xor_sync(0xffffffffu, v1, o);
    }
    if (lane == 0) { sred[0][w] = v0; sred[1][w] = v1; }
    __syncthreads();
    if (tid == 0) {
        float s0 = 0.f, s1 = 0.f;
        #pragma unroll
        for (int k = 0; k < 8; k++) { s0 += sred[0][k]; s1 += sred[1][k]; }
        sInv[0] = 1.0f / fmaxf(s0, 1e-12f);
        sInv[1] = 1.0f / fmaxf(s1, 1e-12f);
    }
    __syncthreads();

    // out[i,h] = inv * sum_{j<=i} score[j] * V[j,h]; split j over 2 halves.
    const int half = tid >> 7;
    const int h    = tid & 127;
    const float* Vb = g_V + b * S_ * H_;
    float a0 = 0.f, a1 = 0.f;
    for (int j = half; j <= i1; j += 2) {
        float v = Vb[j * H_ + h];
        a0 = fmaf(sScore[0][j], v, a0);   // sScore[0][i1] == 0 (masked)
        a1 = fmaf(sScore[1][j], v, a1);
    }
    if (half == 1) { sO[0][h] = a0; sO[1][h] = a1; }
    __syncthreads();
    if (half == 0) {
        out[n0 * H_ + h]        = (a0 + sO[0][h]) * sInv[0];
        out[(n0 + 1) * H_ + h]  = (a1 + sO[1][h]) * sInv[1];
    }
}

// ---------------------------------------------------------------------------
// Launch. Inputs per metadata order: x, Wv, Wq, Wk (all float32).
// ---------------------------------------------------------------------------
extern "C" void kernel_launch(void* const* d_in, const int* in_sizes, int n_in,
                              void* d_out, int out_size)
{
    const float* x  = (const float*)d_in[0];
    const float* Wv = (const float*)d_in[1];
    const float* Wq = (const float*)d_in[2];
    const float* Wk = (const float*)d_in[3];
    float* out = (float*)d_out;

    k1_gemm<<<dim3(16, 10, 2), 256>>>(x, Wq, Wk, Wv);
    k2_probs<<<384, 256>>>(x);
    k3_attn<<<512, 256>>>(out);
}

// round 9
// speedup vs baseline: 2.4684x; 1.1666x over previous
#include <cuda_runtime.h>
#include <math.h>

// Problem constants (fixed by the dataset)
#define B_ 4
#define S_ 256
#define E_ 256
#define H_ 128
#define N_ (B_ * S_)   // 1024 rows total

// Scratch (static device arrays; allocation-free per harness rules)
__device__ float g_ampq2[2][N_ * E_];   // split-K partials
__device__ float g_ampk2[2][N_ * E_];
__device__ float g_V2[2][N_ * H_];
__device__ float g_V[N_ * H_];
__device__ float g_Pq[N_ * E_];   // row-major, query side
__device__ float g_Pk[N_ * E_];   // row-major, key side
__device__ float g_entq[N_];      // sum_e P * lg2(P + 1e-10)
__device__ float g_entk[N_];
__device__ float g_score[N_ * S_];   // masked (pre-normalization) scores

// ---------------------------------------------------------------------------
// Kernel 1: split-K GEMM, now double-buffered.
// C[1024, 640] = x[1024,256] @ [Wq;Wk;Wv]^T.  Proven R8 tiling (64x64 CTA,
// 256 thr, 4x4 micro, 16 FFMA per 2 LDS.128, z = K-half) with the ONLY
// change: 2-deep smem buffers + register prefetch so the next chunk's LDGs
// are in flight during the ~1150-cyc compute block (removes the exposed
// LDG->STS latency that held issue at 45.8%).
// ---------------------------------------------------------------------------
__global__ __launch_bounds__(256) void k1_gemm(
    const float* __restrict__ x,
    const float* __restrict__ Wq,
    const float* __restrict__ Wk,
    const float* __restrict__ Wv)
{
    __shared__ float As[2][32][68];  // [buf][k][m], pad keeps float4 alignment
    __shared__ float Bs[2][32][68];  // [buf][k][f]

    const int m0 = blockIdx.x * 64;       // row tile (0..15)
    const int f0 = blockIdx.y * 64;       // f tile (0..9) over concat 640
    const int z  = blockIdx.z;            // K half
    const int kbase = z * 128;

    const float* Wp; float* outp; int fo, ostride;
    if (f0 < 256)      { Wp = Wq; fo = f0;       outp = g_ampq2[z]; ostride = E_; }
    else if (f0 < 512) { Wp = Wk; fo = f0 - 256; outp = g_ampk2[z]; ostride = E_; }
    else               { Wp = Wv; fo = f0 - 512; outp = g_V2[z];    ostride = H_; }

    const int tid  = threadIdx.x;
    const int tx   = tid & 15;            // f micro
    const int ty   = tid >> 4;            // m micro
    const int lrow = tid >> 2;            // 0..63 loader row
    const int lk   = (tid & 3) * 8;       // 0,8,16,24 loader k base

    const float* xg = x  + (m0 + lrow) * E_ + kbase + lk;
    const float* wg = Wp + (fo + lrow) * E_ + kbase + lk;

    float acc[4][4] = {};

    float4 a0 = *(const float4*)(xg);
    float4 a1 = *(const float4*)(xg + 4);
    float4 b0 = *(const float4*)(wg);
    float4 b1 = *(const float4*)(wg + 4);
    {
        As[0][lk+0][lrow] = a0.x; As[0][lk+1][lrow] = a0.y;
        As[0][lk+2][lrow] = a0.z; As[0][lk+3][lrow] = a0.w;
        As[0][lk+4][lrow] = a1.x; As[0][lk+5][lrow] = a1.y;
        As[0][lk+6][lrow] = a1.z; As[0][lk+7][lrow] = a1.w;
        Bs[0][lk+0][lrow] = b0.x; Bs[0][lk+1][lrow] = b0.y;
        Bs[0][lk+2][lrow] = b0.z; Bs[0][lk+3][lrow] = b0.w;
        Bs[0][lk+4][lrow] = b1.x; Bs[0][lk+5][lrow] = b1.y;
        Bs[0][lk+6][lrow] = b1.z; Bs[0][lk+7][lrow] = b1.w;
    }
    __syncthreads();

    #pragma unroll
    for (int c = 0; c < 4; c++) {
        const int buf = c & 1;
        if (c < 3) {                      // prefetch next chunk BEFORE compute
            const int k0 = (c + 1) * 32;
            a0 = *(const float4*)(xg + k0);
            a1 = *(const float4*)(xg + k0 + 4);
            b0 = *(const float4*)(wg + k0);
            b1 = *(const float4*)(wg + k0 + 4);
        }

        #pragma unroll
        for (int kk = 0; kk < 32; kk++) {
            float4 av = *(const float4*)&As[buf][kk][ty * 4];
            float4 bv = *(const float4*)&Bs[buf][kk][tx * 4];
            acc[0][0] = fmaf(av.x, bv.x, acc[0][0]);
            acc[0][1] = fmaf(av.x, bv.y, acc[0][1]);
            acc[0][2] = fmaf(av.x, bv.z, acc[0][2]);
            acc[0][3] = fmaf(av.x, bv.w, acc[0][3]);
            acc[1][0] = fmaf(av.y, bv.x, acc[1][0]);
            acc[1][1] = fmaf(av.y, bv.y, acc[1][1]);
            acc[1][2] = fmaf(av.y, bv.z, acc[1][2]);
            acc[1][3] = fmaf(av.y, bv.w, acc[1][3]);
            acc[2][0] = fmaf(av.z, bv.x, acc[2][0]);
            acc[2][1] = fmaf(av.z, bv.y, acc[2][1]);
            acc[2][2] = fmaf(av.z, bv.z, acc[2][2]);
            acc[2][3] = fmaf(av.z, bv.w, acc[2][3]);
            acc[3][0] = fmaf(av.w, bv.x, acc[3][0]);
            acc[3][1] = fmaf(av.w, bv.y, acc[3][1]);
            acc[3][2] = fmaf(av.w, bv.z, acc[3][2]);
            acc[3][3] = fmaf(av.w, bv.w, acc[3][3]);
        }

        if (c < 3) {                      // stage next chunk into other buffer
            const int nb = buf ^ 1;
            As[nb][lk+0][lrow] = a0.x; As[nb][lk+1][lrow] = a0.y;
            As[nb][lk+2][lrow] = a0.z; As[nb][lk+3][lrow] = a0.w;
            As[nb][lk+4][lrow] = a1.x; As[nb][lk+5][lrow] = a1.y;
            As[nb][lk+6][lrow] = a1.z; As[nb][lk+7][lrow] = a1.w;
            Bs[nb][lk+0][lrow] = b0.x; Bs[nb][lk+1][lrow] = b0.y;
            Bs[nb][lk+2][lrow] = b0.z; Bs[nb][lk+3][lrow] = b0.w;
            Bs[nb][lk+4][lrow] = b1.x; Bs[nb][lk+5][lrow] = b1.y;
            Bs[nb][lk+6][lrow] = b1.z; Bs[nb][lk+7][lrow] = b1.w;
            __syncthreads();
        }
    }

    #pragma unroll
    for (int i = 0; i < 4; i++) {
        const int row = m0 + ty * 4 + i;
        float4 v = make_float4(acc[i][0], acc[i][1], acc[i][2], acc[i][3]);
        *(float4*)&outp[row * ostride + fo + tx * 4] = v;
    }
}

// ---------------------------------------------------------------------------
// Kernel 2 (unchanged, proven): warp-per-row split-K combine + probs +
// entropy.  Regions 0/1 (q/k): amp = part0+part1, P = amp^2/(ssq+EPS*d^2),
// ent = sum P*lg2(P+EPS).  Region 2: V = V0+V1.  grid 384 x 256.
// ---------------------------------------------------------------------------
__global__ __launch_bounds__(256) void k2_probs(const float* __restrict__ x)
{
    const int w    = threadIdx.x >> 5;
    const int lane = threadIdx.x & 31;
    const int slot = blockIdx.x * 8 + w;       // 0..3071
    const int regn = slot >> 10;               // 0 = q, 1 = k, 2 = V-combine
    const int n    = slot & 1023;

    if (regn == 2) {
        const float4* v0 = (const float4*)&g_V2[0][n * H_];
        const float4* v1 = (const float4*)&g_V2[1][n * H_];
        float4*       vo = (float4*)&g_V[n * H_];
        const float4 a = v0[lane], b = v1[lane];
        vo[lane] = make_float4(a.x + b.x, a.y + b.y, a.z + b.z, a.w + b.w);
        return;
    }

    const float* a0 = (regn ? g_ampk2[0] : g_ampq2[0]) + n * E_;
    const float* a1 = (regn ? g_ampk2[1] : g_ampq2[1]) + n * E_;
    float*     Pout = (regn ? g_Pk       : g_Pq)       + n * E_;
    const float* xr = x + n * E_;

    float a[8];
    float ssa = 0.f, ssx = 0.f;
    #pragma unroll
    for (int m = 0; m < 8; m++) {
        a[m] = a0[lane + 32 * m] + a1[lane + 32 * m];
        float xv = xr[lane + 32 * m];
        ssa = fmaf(a[m], a[m], ssa);
        ssx = fmaf(xv, xv, ssx);
    }
    #pragma unroll
    for (int o = 16; o; o >>= 1) {
        ssa += __shfl_xor_sync(0xffffffffu, ssa, o);
        ssx += __shfl_xor_sync(0xffffffffu, ssx, o);
    }
    const float d   = sqrtf(ssx) + 1e-12f;
    const float inv = 1.0f / (ssa + 1e-10f * d * d);

    float ent = 0.f;
    #pragma unroll
    for (int m = 0; m < 8; m++) {
        const float P = a[m] * a[m] * inv;
        ent = fmaf(P, __log2f(P + 1e-10f), ent);
        Pout[lane + 32 * m] = P;
    }
    #pragma unroll
    for (int o = 16; o; o >>= 1)
        ent += __shfl_xor_sync(0xffffffffu, ent, o);
    if (lane == 0) (regn ? g_entk : g_entq)[n] = ent;
}

// ---------------------------------------------------------------------------
// Kernel 3a: JS scores, shuffle-free.  CTA = (8-row block, 32-j block, batch);
// grid (32, 8, 4), fully-masked blocks exit immediately (576 live CTAs,
// ~12% rectangle overshoot over the causal triangle).  Pk rows staged into
// smem with stride-257 padding so the column read sPk[lane][e] is
// conflict-free ((lane+e) mod 32 all distinct).  Warp w owns row i0+w,
// lane owns j0+lane; inner loop has NO shfl and NO gmem loads:
// per 4e = LDS.128(p) + 4 LDS(q) + 4x(FADD, FFMA, MUFU.LG2, FFMA).
// MUFU-bound: ~37.7M lg2 / 2368 lanes/cyc ~ 9 us.
// ---------------------------------------------------------------------------
__global__ __launch_bounds__(256) void k3a_score()
{
    const int rb = blockIdx.x;         // row block: rows 8rb..8rb+7
    const int jb = blockIdx.y;         // j block:   js  32jb..32jb+31
    const int b  = blockIdx.z;
    if (jb > (rb >> 2)) return;        // whole block above the diagonal

    __shared__ float sPk[32][257];     // [j_local][e], stride 257
    __shared__ float sP[8][256];       // [row_local][e]
    __shared__ float sHk[32];

    const int tid  = threadIdx.x;
    const int w    = tid >> 5;
    const int lane = tid & 31;
    const int i0 = rb * 8, j0 = jb * 32;

    // Stage Pk rows (warp w -> rows 4w..4w+3; 8 lanes per row, coalesced 128B)
    {
        const int row = 4 * w + (lane >> 3);
        const int fb  = lane & 7;
        const float* src = g_Pk + (b * S_ + j0 + row) * E_;
        #pragma unroll
        for (int it = 0; it < 8; it++) {
            const int f = fb + 8 * it;          // float4 index within row
            float4 v = *(const float4*)(src + 4 * f);
            sPk[row][4*f+0] = v.x; sPk[row][4*f+1] = v.y;
            sPk[row][4*f+2] = v.z; sPk[row][4*f+3] = v.w;
        }
    }
    // Stage Pq rows (warp w -> row w, two float4 per lane, coalesced)
    {
        const float* src = g_Pq + (b * S_ + i0 + w) * E_;
        *(float4*)&sP[w][4 * lane]        = *(const float4*)(src + 4 * lane);
        *(float4*)&sP[w][128 + 4 * lane]  = *(const float4*)(src + 128 + 4 * lane);
    }
    if (tid < 32) sHk[tid] = g_entk[b * S_ + j0 + tid];
    __syncthreads();

    const float hq = g_entq[b * S_ + i0 + w];
    const float hk = sHk[lane];

    float ac0 = 0.f, ac1 = 0.f, ac2 = 0.f, ac3 = 0.f;
    #pragma unroll 8
    for (int e = 0; e < E_; e += 4) {
        const float4 p = *(const float4*)&sP[w][e];
        const float s0 = p.x + sPk[lane][e + 0];
        const float s1 = p.y + sPk[lane][e + 1];
        const float s2 = p.z + sPk[lane][e + 2];
        const float s3 = p.w + sPk[lane][e + 3];
        ac0 = fmaf(s0, __log2f(fmaf(0.5f, s0, 1e-10f)), ac0);
        ac1 = fmaf(s1, __log2f(fmaf(0.5f, s1, 1e-10f)), ac1);
        ac2 = fmaf(s2, __log2f(fmaf(0.5f, s2, 1e-10f)), ac2);
        ac3 = fmaf(s3, __log2f(fmaf(0.5f, s3, 1e-10f)), ac3);
    }
    const float acc = (ac0 + ac1) + (ac2 + ac3);

    const int i = i0 + w, j = j0 + lane;
    const float HL = 0.34657359028f;             // 0.5 * ln(2)
    const float score = 1.0f - HL * (hq + hk - acc);
    g_score[(b * S_ + i) * S_ + j] = (j <= i) ? score : 0.0f;   // coalesced
}

// ---------------------------------------------------------------------------
// Kernel 3b: row L1-normalize + attn @ V (R5's proven tail, scores from
// gmem).  One CTA per two adjacent query rows; 512 CTAs x 256 threads.
// ---------------------------------------------------------------------------
__global__ __launch_bounds__(256) void k3b_out(float* __restrict__ out)
{
    __shared__ float sScore[2][256];
    __shared__ float sO[2][128];
    __shared__ float sred[2][8];
    __shared__ float sInv[2];

    const int c  = blockIdx.x;        // 0..511
    const int n0 = c * 2;
    const int b  = n0 >> 8;
    const int i0 = n0 & 255;
    const int i1 = i0 + 1;
    const int tid  = threadIdx.x;
    const int w    = tid >> 5;
    const int lane = tid & 31;

    const float v0 = (tid <= i0) ? g_score[n0 * S_ + tid]       : 0.f;
    const float v1 = (tid <= i1) ? g_score[(n0 + 1) * S_ + tid] : 0.f;
    sScore[0][tid] = v0;
    sScore[1][tid] = v1;

    float r0 = fabsf(v0), r1 = fabsf(v1);
    #pragma unroll
    for (int o = 16; o; o >>= 1) {
        r0 += __shfl_xor_sync(0xffffffffu, r0, o);
        r1 += __shfl_xor_sync(0xffffffffu, r1, o);
    }
    if (lane == 0) { sred[0][w] = r0; sred[1][w] = r1; }
    __syncthreads();
    if (tid == 0) {
        float s0 = 0.f, s1 = 0.f;
        #pragma unroll
        for (int k = 0; k < 8; k++) { s0 += sred[0][k]; s1 += sred[1][k]; }
        sInv[0] = 1.0f / fmaxf(s0, 1e-12f);
        sInv[1] = 1.0f / fmaxf(s1, 1e-12f);
    }
    __syncthreads();

    // out[i,h] = inv * sum_{j<=i} score[j] * V[j,h]; split j over 2 halves.
    const int half = tid >> 7;
    const int h    = tid & 127;
    const float* Vb = g_V + b * S_ * H_;
    float a0 = 0.f, a1 = 0.f;
    for (int j = half; j <= i1; j += 2) {
        const float v = Vb[j * H_ + h];
        a0 = fmaf(sScore[0][j], v, a0);   // masked entries are exactly 0
        a1 = fmaf(sScore[1][j], v, a1);
    }
    if (half == 1) { sO[0][h] = a0; sO[1][h] = a1; }
    __syncthreads();
    if (half == 0) {
        out[n0 * H_ + h]       = (a0 + sO[0][h]) * sInv[0];
        out[(n0 + 1) * H_ + h] = (a1 + sO[1][h]) * sInv[1];
    }
}

// ---------------------------------------------------------------------------
// Launch. Inputs per metadata order: x, Wv, Wq, Wk (all float32).
// ---------------------------------------------------------------------------
extern "C" void kernel_launch(void* const* d_in, const int* in_sizes, int n_in,
                              void* d_out, int out_size)
{
    const float* x  = (const float*)d_in[0];
    const float* Wv = (const float*)d_in[1];
    const float* Wq = (const float*)d_in[2];
    const float* Wk = (const float*)d_in[3];
    float* out = (float*)d_out;

    k1_gemm<<<dim3(16, 10, 2), 256>>>(x, Wq, Wk, Wv);
    k2_probs<<<384, 256>>>(x);
    k3a_score<<<dim3(32, 8, 4), 256>>>();
    k3b_out<<<512, 256>>>(out);
}